// round 4
// baseline (speedup 1.0000x reference)
#include <cuda_runtime.h>

#define TB   32
#define NTH  256

// smem floats: yR 2048, xR 2048, hA 8192, hB 8192, sS 2048, sT 2048,
//              bias1 256, bias2 256, b3 64, sc 64, mv 64, ld 32
#define SMEM_FLOATS (2048+2048+8192+8192+2048+2048+256+256+64+64+64+32)
#define SMEM_BYTES  (SMEM_FLOATS*4)

// Transposed weight scratch: [net][layer][K][N] layouts
__device__ __align__(256) float g_W1t[2][8*64*256];   // [k=64][n=256]
__device__ __align__(256) float g_W2t[2][8*256*256];  // [k=256][n=256]
__device__ __align__(256) float g_W3t[2][8*256*64];   // [k=256][n=64]

// ---------------- weight transpose ----------------
__global__ void tr_all(const float* __restrict__ sW1, const float* __restrict__ sW2,
                       const float* __restrict__ sW3, const float* __restrict__ tW1,
                       const float* __restrict__ tW2, const float* __restrict__ tW3)
{
    int tid = blockIdx.x * blockDim.x + threadIdx.x;
    int nt  = gridDim.x * blockDim.x;
    // W1 [8][256][64] -> [8][64][256]; W3 [8][64][256] -> [8][256][64]
    for (int i = tid; i < 8*256*64; i += nt) {
        int l = i >> 14, rem = i & 16383;
        int r = rem >> 6, c = rem & 63;              // W1: r=n(256), c=k(64)
        g_W1t[0][(l<<14) + (c<<8) + r] = sW1[i];
        g_W1t[1][(l<<14) + (c<<8) + r] = tW1[i];
        int r3 = rem >> 8, c3 = rem & 255;           // W3: r3=n(64), c3=k(256)
        g_W3t[0][(l<<14) + (c3<<6) + r3] = sW3[i];
        g_W3t[1][(l<<14) + (c3<<6) + r3] = tW3[i];
    }
    // W2 [8][256][256] -> [8][256][256] transposed
    for (int i = tid; i < 8*256*256; i += nt) {
        int l = i >> 16, rem = i & 65535;
        int r = rem >> 8, c = rem & 255;
        float v0 = sW2[i], v1 = tW2[i];
        g_W2t[0][(l<<16) + (c<<8) + r] = v0;
        g_W2t[1][(l<<16) + (c<<8) + r] = v1;
    }
}

// ---------------- helpers ----------------
__device__ __forceinline__ float tanh_fast(float x) {
    float e = __expf(2.0f * x);
    return 1.0f - __fdividef(2.0f, e + 1.0f);
}
__device__ __forceinline__ unsigned long long dup2(float x) {
    unsigned long long r;
    asm("mov.b64 %0, {%1, %1};" : "=l"(r) : "f"(x));
    return r;
}
__device__ __forceinline__ void fma2(unsigned long long& d, unsigned long long a,
                                     unsigned long long b) {
    asm("fma.rn.f32x2 %0, %1, %2, %0;" : "+l"(d) : "l"(a), "l"(b));
}
__device__ __forceinline__ float2 unpack2(unsigned long long v) {
    float lo, hi;
    asm("mov.b64 {%0, %1}, %2;" : "=f"(lo), "=f"(hi) : "l"(v));
    return make_float2(lo, hi);
}

// ---------------- GEMM N=256 (G1 / G2) ----------------
// out[r][c] = tanh( sum_k in[r][k]*Wt[k][c] + bias[c] (+ in[r][c] if SKIP) )
template<int K, int INSTRIDE, bool SKIP>
__device__ __forceinline__ void gemmN256(const float* __restrict__ Wt,
                                         const float* __restrict__ in,
                                         float* __restrict__ out,
                                         const float* __restrict__ bias, int tid)
{
    const int cg = tid & 31, rg = tid >> 5;
    const int cA = cg << 2;            // cols cA..cA+3
    const int cB = 128 + (cg << 2);    // cols cB..cB+3
    const int r0 = rg << 2;

    unsigned long long acc[4][4];
#pragma unroll
    for (int r = 0; r < 4; r++)
#pragma unroll
        for (int p = 0; p < 4; p++) acc[r][p] = 0ull;

    const float* in0 = in + (r0 + 0) * INSTRIDE;
    const float* in1 = in + (r0 + 1) * INSTRIDE;
    const float* in2 = in + (r0 + 2) * INSTRIDE;
    const float* in3 = in + (r0 + 3) * INSTRIDE;

#pragma unroll 2
    for (int k0 = 0; k0 < K; k0 += 4) {
        float4 a0 = *reinterpret_cast<const float4*>(in0 + k0);
        float4 a1 = *reinterpret_cast<const float4*>(in1 + k0);
        float4 a2 = *reinterpret_cast<const float4*>(in2 + k0);
        float4 a3 = *reinterpret_cast<const float4*>(in3 + k0);
#define KSTEP(kk, e0, e1, e2, e3)                                                  \
        {                                                                          \
            const float* wrow = Wt + (k0 + kk) * 256;                              \
            ulonglong2 wA = *reinterpret_cast<const ulonglong2*>(wrow + cA);       \
            ulonglong2 wB = *reinterpret_cast<const ulonglong2*>(wrow + cB);       \
            unsigned long long d0 = dup2(e0), d1 = dup2(e1);                       \
            unsigned long long d2 = dup2(e2), d3 = dup2(e3);                       \
            fma2(acc[0][0], d0, wA.x); fma2(acc[0][1], d0, wA.y);                  \
            fma2(acc[0][2], d0, wB.x); fma2(acc[0][3], d0, wB.y);                  \
            fma2(acc[1][0], d1, wA.x); fma2(acc[1][1], d1, wA.y);                  \
            fma2(acc[1][2], d1, wB.x); fma2(acc[1][3], d1, wB.y);                  \
            fma2(acc[2][0], d2, wA.x); fma2(acc[2][1], d2, wA.y);                  \
            fma2(acc[2][2], d2, wB.x); fma2(acc[2][3], d2, wB.y);                  \
            fma2(acc[3][0], d3, wA.x); fma2(acc[3][1], d3, wA.y);                  \
            fma2(acc[3][2], d3, wB.x); fma2(acc[3][3], d3, wB.y);                  \
        }
        KSTEP(0, a0.x, a1.x, a2.x, a3.x)
        KSTEP(1, a0.y, a1.y, a2.y, a3.y)
        KSTEP(2, a0.z, a1.z, a2.z, a3.z)
        KSTEP(3, a0.w, a1.w, a2.w, a3.w)
#undef KSTEP
    }

    float4 bA = *reinterpret_cast<const float4*>(&bias[cA]);
    float4 bB = *reinterpret_cast<const float4*>(&bias[cB]);
#pragma unroll
    for (int r = 0; r < 4; r++) {
        float2 vA0 = unpack2(acc[r][0]), vA1 = unpack2(acc[r][1]);
        float2 vB0 = unpack2(acc[r][2]), vB1 = unpack2(acc[r][3]);
        float oA0 = vA0.x + bA.x, oA1 = vA0.y + bA.y;
        float oA2 = vA1.x + bA.z, oA3 = vA1.y + bA.w;
        float oB0 = vB0.x + bB.x, oB1 = vB0.y + bB.y;
        float oB2 = vB1.x + bB.z, oB3 = vB1.y + bB.w;
        if (SKIP) {
            const float* irow = in + (r0 + r) * INSTRIDE;
            float4 sA = *reinterpret_cast<const float4*>(&irow[cA]);
            float4 sB = *reinterpret_cast<const float4*>(&irow[cB]);
            oA0 += sA.x; oA1 += sA.y; oA2 += sA.z; oA3 += sA.w;
            oB0 += sB.x; oB1 += sB.y; oB2 += sB.z; oB3 += sB.w;
        }
        float* orow = out + (r0 + r) * 256;
        float4 wOA = make_float4(tanh_fast(oA0), tanh_fast(oA1),
                                 tanh_fast(oA2), tanh_fast(oA3));
        float4 wOB = make_float4(tanh_fast(oB0), tanh_fast(oB1),
                                 tanh_fast(oB2), tanh_fast(oB3));
        *reinterpret_cast<float4*>(&orow[cA]) = wOA;
        *reinterpret_cast<float4*>(&orow[cB]) = wOB;
    }
}

// ---------------- GEMM N=64 (G3, both nets) ----------------
// SNET:  out = (tanh(acc + b3[c]) + xm[r][c]) * sc[c]
// !SNET: out = acc + b3[c] + xm[r][c]
template<bool SNET>
__device__ __forceinline__ void gemm64f(const float* __restrict__ Wt,  // [256][64]
                                        const float* __restrict__ in,  // [TB][256]
                                        const float* __restrict__ xmr, // [TB][64]
                                        float* __restrict__ outr,      // [TB][64]
                                        const float* __restrict__ b3,
                                        const float* __restrict__ sc, int tid)
{
    const int cg = tid & 31, rg = tid >> 5;
    const int c0 = cg << 1, r0 = rg << 2;
    unsigned long long acc[4] = {0ull, 0ull, 0ull, 0ull};

    const float* in0 = in + (r0 + 0) * 256;
    const float* in1 = in + (r0 + 1) * 256;
    const float* in2 = in + (r0 + 2) * 256;
    const float* in3 = in + (r0 + 3) * 256;

#pragma unroll 2
    for (int k0 = 0; k0 < 256; k0 += 4) {
        float4 a0 = *reinterpret_cast<const float4*>(in0 + k0);
        float4 a1 = *reinterpret_cast<const float4*>(in1 + k0);
        float4 a2 = *reinterpret_cast<const float4*>(in2 + k0);
        float4 a3 = *reinterpret_cast<const float4*>(in3 + k0);
#define K64(kk, e0, e1, e2, e3)                                                     \
        {                                                                           \
            unsigned long long w =                                                  \
                *reinterpret_cast<const unsigned long long*>(Wt + (k0+kk)*64 + c0); \
            fma2(acc[0], dup2(e0), w); fma2(acc[1], dup2(e1), w);                   \
            fma2(acc[2], dup2(e2), w); fma2(acc[3], dup2(e3), w);                   \
        }
        K64(0, a0.x, a1.x, a2.x, a3.x)
        K64(1, a0.y, a1.y, a2.y, a3.y)
        K64(2, a0.z, a1.z, a2.z, a3.z)
        K64(3, a0.w, a1.w, a2.w, a3.w)
#undef K64
    }

    float2 b = *reinterpret_cast<const float2*>(&b3[c0]);
    float2 scv = make_float2(0.f, 0.f);
    if (SNET) scv = *reinterpret_cast<const float2*>(&sc[c0]);
#pragma unroll
    for (int r = 0; r < 4; r++) {
        float2 v  = unpack2(acc[r]);
        float2 xm = *reinterpret_cast<const float2*>(&xmr[(r0 + r) * 64 + c0]);
        float o0, o1;
        if (SNET) {
            o0 = (tanh_fast(v.x + b.x) + xm.x) * scv.x;
            o1 = (tanh_fast(v.y + b.y) + xm.y) * scv.y;
        } else {
            o0 = v.x + b.x + xm.x;
            o1 = v.y + b.y + xm.y;
        }
        *reinterpret_cast<float2*>(&outr[(r0 + r) * 64 + c0]) = make_float2(o0, o1);
    }
}

// ---------------- main flow kernel ----------------
__global__ void __launch_bounds__(NTH, 2)
flow_kernel(const float* __restrict__ x, const float* __restrict__ masks,
            const float* __restrict__ sb1, const float* __restrict__ sb2,
            const float* __restrict__ sb3, const float* __restrict__ scale,
            const float* __restrict__ tb1, const float* __restrict__ tb2,
            const float* __restrict__ tb3,
            float* __restrict__ out, int B, long long ld_off)
{
    extern __shared__ float sm[];
    float* yR    = sm;            // [32][64]
    float* xR    = yR + 2048;     // [32][64]
    float* hA    = xR + 2048;     // [32][256]
    float* hB    = hA + 8192;     // [32][256]
    float* sS    = hB + 8192;     // [32][64]
    float* sT    = sS + 2048;     // [32][64]
    float* bias1 = sT + 2048;     // [256]
    float* bias2 = bias1 + 256;   // [256]
    float* b3s   = bias2 + 256;   // [64]
    float* scs   = b3s + 64;      // [64]
    float* mv    = scs + 64;      // [64]
    float* ldac  = mv + 64;       // [32]

    const int tid = threadIdx.x;
    const int gb  = blockIdx.x * TB;

    // load y tile (coalesced, row-major matches global)
    for (int i = tid; i < TB * 64; i += NTH) yR[i] = x[(long long)gb * 64 + i];
    if (tid < TB) ldac[tid] = 0.f;
    __syncthreads();

    for (int layer = 0; layer < 8; layer++) {
        if (tid < 64) mv[tid] = masks[layer * 64 + tid];
        __syncthreads();
        for (int i = tid; i < TB * 64; i += NTH) xR[i] = yR[i] * mv[i & 63];

#pragma unroll 1
        for (int net = 0; net < 2; net++) {
            const float* W1 = &g_W1t[net][layer * (64 * 256)];
            const float* W2 = &g_W2t[net][layer * (256 * 256)];
            const float* W3 = &g_W3t[net][layer * (256 * 64)];
            const float* b1 = (net ? tb1 : sb1) + layer * 256;
            const float* b2 = (net ? tb2 : sb2) + layer * 256;
            const float* b3 = (net ? tb3 : sb3) + layer * 64;
            bias1[tid] = b1[tid];
            bias2[tid] = b2[tid];
            if (tid < 64) {
                b3s[tid] = b3[tid];
                if (net == 0) scs[tid] = scale[layer * 64 + tid];
            }
            __syncthreads();
            gemmN256<64, 64, false>(W1, xR, hA, bias1, tid);
            __syncthreads();
            gemmN256<256, 256, true>(W2, hA, hB, bias2, tid);
            __syncthreads();
            if (net == 0) gemm64f<true >(W3, hB, xR, sS, b3s, scs, tid);
            else          gemm64f<false>(W3, hB, xR, sT, b3s, scs, tid);
            __syncthreads();
        }

        // coupling update + logdet
        {
            const int r  = tid >> 3;       // 0..31
            const int db = tid & 7;        // 0..7
            const int d0 = db << 3;        // 8 consecutive d per thread
            float part = 0.f;
#pragma unroll
            for (int v = 0; v < 2; v++) {
                int d = d0 + v * 4;
                float4 yv = *reinterpret_cast<const float4*>(&yR[r * 64 + d]);
                float4 s4 = *reinterpret_cast<const float4*>(&sS[r * 64 + d]);
                float4 t4 = *reinterpret_cast<const float4*>(&sT[r * 64 + d]);
                float4 m4 = *reinterpret_cast<const float4*>(&mv[d]);
                float4 yn;
                {
                    float im = 1.f - m4.x;
                    yn.x = m4.x * yv.x + im * (yv.x * __expf(s4.x) + t4.x);
                    part += im * s4.x;
                }
                {
                    float im = 1.f - m4.y;
                    yn.y = m4.y * yv.y + im * (yv.y * __expf(s4.y) + t4.y);
                    part += im * s4.y;
                }
                {
                    float im = 1.f - m4.z;
                    yn.z = m4.z * yv.z + im * (yv.z * __expf(s4.z) + t4.z);
                    part += im * s4.z;
                }
                {
                    float im = 1.f - m4.w;
                    yn.w = m4.w * yv.w + im * (yv.w * __expf(s4.w) + t4.w);
                    part += im * s4.w;
                }
                *reinterpret_cast<float4*>(&yR[r * 64 + d]) = yn;
            }
            part += __shfl_down_sync(0xffffffffu, part, 4, 8);
            part += __shfl_down_sync(0xffffffffu, part, 2, 8);
            part += __shfl_down_sync(0xffffffffu, part, 1, 8);
            if (db == 0) ldac[r] += part;
        }
        __syncthreads();
    }

    // write y and logdet
    for (int i = tid; i < TB * 64; i += NTH) out[(long long)gb * 64 + i] = yR[i];
    if (tid < TB) out[ld_off + gb + tid] = ldac[tid];
}

// ---------------- launch ----------------
extern "C" void kernel_launch(void* const* d_in, const int* in_sizes, int n_in,
                              void* d_out, int out_size)
{
    const float* x     = (const float*)d_in[0];
    const float* masks = (const float*)d_in[1];
    const float* sW1   = (const float*)d_in[2];
    const float* sb1   = (const float*)d_in[3];
    const float* sW2   = (const float*)d_in[4];
    const float* sb2   = (const float*)d_in[5];
    const float* sW3   = (const float*)d_in[6];
    const float* sb3   = (const float*)d_in[7];
    const float* scale = (const float*)d_in[8];
    const float* tW1   = (const float*)d_in[9];
    const float* tb1   = (const float*)d_in[10];
    const float* tW2   = (const float*)d_in[11];
    const float* tb2   = (const float*)d_in[12];
    const float* tW3   = (const float*)d_in[13];
    const float* tb3   = (const float*)d_in[14];

    const int B = in_sizes[0] / 64;
    const long long ld_off = (long long)out_size - B;  // y first, logdet last

    cudaFuncSetAttribute(flow_kernel, cudaFuncAttributeMaxDynamicSharedMemorySize,
                         SMEM_BYTES);

    tr_all<<<256, 256>>>(sW1, sW2, sW3, tW1, tW2, tW3);
    flow_kernel<<<B / TB, NTH, SMEM_BYTES>>>(x, masks, sb1, sb2, sb3, scale,
                                             tb1, tb2, tb3, (float*)d_out, B,
                                             ld_off);
}

// round 6
// speedup vs baseline: 1.9586x; 1.9586x over previous
#include <cuda_runtime.h>
#include <cuda_bf16.h>
#include <cstdint>

typedef unsigned int u32;

// ---- SMEM layout (byte offsets) ----
#define O_H    0         // uint2 h[128][130]  (bf16 hi-pair, lo-pair)
#define O_Y    133120    // float y[128][68]
#define O_BST  167936    // uint4 stage[2][1024]  (2 x 16KB)
#define O_LDP  200704    // float ldp[128][4]
#define O_MASK 202752    // float[64]
#define O_B1   203008    // float[256]
#define O_B2   204032    // float[256]
#define O_B3   205056    // float[64]
#define O_SC   205312    // float[64]
#define SMEM_REQ 205568

#define LNB 393216                // bytes per (layer,net) weight block
__device__ __align__(256) unsigned char g_wb[16u * LNB];

// ---------------- helpers ----------------
__device__ __forceinline__ float tanhf_(float x) {
    float e = __expf(2.0f * x);
    return 1.0f - __fdividef(2.0f, e + 1.0f);
}
__device__ __forceinline__ uint2 splitp(float v0, float v1) {
    __nv_bfloat162 h = __floats2bfloat162_rn(v0, v1);
    float h0 = __bfloat162float(h.x), h1 = __bfloat162float(h.y);
    __nv_bfloat162 l = __floats2bfloat162_rn(v0 - h0, v1 - h1);
    uint2 r; r.x = *(u32*)&h; r.y = *(u32*)&l; return r;
}
__device__ __forceinline__ float2 unpb(u32 w) {
    __nv_bfloat162 t = *(__nv_bfloat162*)&w;
    return __bfloat1622float2(t);
}
__device__ __forceinline__ void mma16816(float* d, u32 a0, u32 a1, u32 a2, u32 a3,
                                         u32 b0, u32 b1) {
    asm volatile(
        "mma.sync.aligned.m16n8k16.row.col.f32.bf16.bf16.f32 "
        "{%0,%1,%2,%3}, {%4,%5,%6,%7}, {%8,%9}, {%0,%1,%2,%3};"
        : "+f"(d[0]), "+f"(d[1]), "+f"(d[2]), "+f"(d[3])
        : "r"(a0), "r"(a1), "r"(a2), "r"(a3), "r"(b0), "r"(b1));
}

// ---------------- prep: pack weights into per-lane B-fragment layout ----------------
// Per (layer,net) block (393216B): G1 @0 (4 ks x 16KB), G2 @65536 (16 x 16KB),
// G3 @327680 (16 x 4KB). Slab = [nt][lane] x {b0hi,b1hi,b0lo,b1lo} (16B).
__global__ void prep(const float* __restrict__ sW1, const float* __restrict__ sW2,
                     const float* __restrict__ sW3, const float* __restrict__ tW1,
                     const float* __restrict__ tW2, const float* __restrict__ tW3)
{
    int t = blockIdx.x * blockDim.x + threadIdx.x;       // 0 .. 393215
    int ln = t / 24576, rem = t % 24576;
    int l = ln >> 1, net = ln & 1;
    int g, ks, nt, lane;
    if (rem < 4096)       { g = 0; ks = rem >> 10; nt = (rem >> 5) & 31; lane = rem & 31; }
    else if (rem < 20480) { int q = rem - 4096;  g = 1; ks = q >> 10; nt = (q >> 5) & 31; lane = q & 31; }
    else                  { int q = rem - 20480; g = 2; ks = q >> 8;  nt = (q >> 5) & 7;  lane = q & 31; }

    int n = nt * 8 + (lane >> 2);
    int k = ks * 16 + (lane & 3) * 2;
    const float* Wp; long base; int kst;
    if (g == 0)      { Wp = net ? tW1 : sW1; base = (long)l * 16384; kst = 64;  }
    else if (g == 1) { Wp = net ? tW2 : sW2; base = (long)l * 65536; kst = 256; }
    else             { Wp = net ? tW3 : sW3; base = (long)l * 16384; kst = 256; }

    const float* wr = Wp + base + (long)n * kst + k;
    float w00 = wr[0], w01 = wr[1], w10 = wr[8], w11 = wr[9];
    uint2 p0 = splitp(w00, w01);
    uint2 p1 = splitp(w10, w11);
    size_t off = (size_t)ln * LNB + (g == 0 ? 0 : (g == 1 ? 65536 : 327680))
               + (size_t)((g == 2 ? (ks * 8 + nt) : (ks * 32 + nt)) * 512 + lane * 16);
    *(uint4*)(g_wb + off) = make_uint4(p0.x, p1.x, p0.y, p1.y);
}

// ---------------- GEMM: D[128, NTT*8] = A[128,K] @ W^T, acc in registers ----------------
template<int KS, int NTW, int SLAB, bool AXM>
__device__ __forceinline__ void run_gemm(float (&acc)[2][8][4],
                                         const unsigned char* __restrict__ Bg,
                                         char* smc, int tid, int lane,
                                         int mprow, int nq)
{
#pragma unroll
    for (int mt = 0; mt < 2; mt++)
#pragma unroll
        for (int j = 0; j < NTW; j++)
#pragma unroll
            for (int i = 0; i < 4; i++) acc[mt][j][i] = 0.f;

    const uint4* gsrc = (const uint4*)Bg;
    uint4* bst = (uint4*)(smc + O_BST);
    const int C16 = SLAB / 16;            // uint4 per slab
    int i0 = tid, i1 = tid + 512;
    bool u0 = (i0 < C16), u1 = (i1 < C16);
    uint4 pv0, pv1;
    if (u0) pv0 = gsrc[i0];
    if (u1) pv1 = gsrc[i1];
    __syncthreads();
    if (u0) bst[i0] = pv0;
    if (u1) bst[i1] = pv1;
    if (KS > 1) { if (u0) pv0 = gsrc[C16 + i0]; if (u1) pv1 = gsrc[C16 + i1]; }
    __syncthreads();

#pragma unroll 1
    for (int ks = 0; ks < KS; ks++) {
        if (ks + 1 < KS) {
            uint4* d = bst + ((ks + 1) & 1) * 1024;
            if (u0) d[i0] = pv0;
            if (u1) d[i1] = pv1;
            if (ks + 2 < KS) {
                const uint4* s = gsrc + (size_t)(ks + 2) * C16;
                if (u0) pv0 = s[i0];
                if (u1) pv1 = s[i1];
            }
        }
        const uint4* bb = bst + (ks & 1) * 1024 + nq * NTW * 32 + lane;
#pragma unroll
        for (int mt = 0; mt < 2; mt++) {
            int r1 = mprow + mt * 16 + (lane >> 2);
            u32 A0h, A1h, A2h, A3h, A0l, A1l, A2l, A3l;
            if (AXM) {
                const float* yr1 = (const float*)(smc + O_Y) + r1 * 68;
                const float* yr2 = yr1 + 8 * 68;
                const float* mk = (const float*)(smc + O_MASK);
                int c = ks * 16 + (lane & 3) * 2;
                float m0 = mk[c], m1 = mk[c + 1], m8 = mk[c + 8], m9 = mk[c + 9];
                float2 v;
                v = *(const float2*)(yr1 + c);     { uint2 q = splitp(v.x * m0, v.y * m1); A0h = q.x; A0l = q.y; }
                v = *(const float2*)(yr2 + c);     { uint2 q = splitp(v.x * m0, v.y * m1); A1h = q.x; A1l = q.y; }
                v = *(const float2*)(yr1 + c + 8); { uint2 q = splitp(v.x * m8, v.y * m9); A2h = q.x; A2l = q.y; }
                v = *(const float2*)(yr2 + c + 8); { uint2 q = splitp(v.x * m8, v.y * m9); A3h = q.x; A3l = q.y; }
            } else {
                const uint2* p = (const uint2*)(smc + O_H) + r1 * 130 + ks * 8 + (lane & 3);
                uint2 t0 = p[0], t2 = p[4], t1 = p[8 * 130], t3 = p[8 * 130 + 4];
                A0h = t0.x; A0l = t0.y; A1h = t1.x; A1l = t1.y;
                A2h = t2.x; A2l = t2.y; A3h = t3.x; A3l = t3.y;
            }
#pragma unroll
            for (int j = 0; j < NTW; j++) {
                uint4 b = bb[j * 32];
                mma16816(acc[mt][j], A0h, A1h, A2h, A3h, b.x, b.y);
                mma16816(acc[mt][j], A0l, A1l, A2l, A3l, b.x, b.y);
                mma16816(acc[mt][j], A0h, A1h, A2h, A3h, b.z, b.w);
            }
        }
        __syncthreads();
    }
}

// ---------------- epilogues ----------------
template<bool RES>
__device__ __forceinline__ void epi_h(float (&acc)[2][8][4], const float* bias,
                                      char* smc, int lane, int mprow, int nq)
{
    uint2* hb = (uint2*)(smc + O_H);
#pragma unroll
    for (int mt = 0; mt < 2; mt++) {
        int r1 = mprow + mt * 16 + (lane >> 2);
#pragma unroll
        for (int j = 0; j < 8; j++) {
            int c2 = nq * 32 + j * 4 + (lane & 3);
            int c = c2 * 2;
            float b0 = bias[c], b1 = bias[c + 1];
            uint2* p = hb + r1 * 130 + c2;
            float u0 = acc[mt][j][0] + b0, u1 = acc[mt][j][1] + b1;
            float u2 = acc[mt][j][2] + b0, u3 = acc[mt][j][3] + b1;
            if (RES) {
                uint2 q0 = p[0], q1 = p[8 * 130];
                float2 h0 = unpb(q0.x), l0 = unpb(q0.y);
                float2 h1 = unpb(q1.x), l1 = unpb(q1.y);
                u0 += h0.x + l0.x; u1 += h0.y + l0.y;
                u2 += h1.x + l1.x; u3 += h1.y + l1.y;
            }
            p[0]       = splitp(tanhf_(u0), tanhf_(u1));
            p[8 * 130] = splitp(tanhf_(u2), tanhf_(u3));
        }
    }
}

template<bool SNET>
__device__ __forceinline__ void epi_g3(float (&acc)[2][8][4], char* smc,
                                       int lane, int mprow, int nq)
{
    float* yb = (float*)(smc + O_Y);
    const float* mk = (const float*)(smc + O_MASK);
    const float* b3 = (const float*)(smc + O_B3);
    const float* sc = (const float*)(smc + O_SC);
    float* ldp = (float*)(smc + O_LDP);
    float p[4] = {0.f, 0.f, 0.f, 0.f};
#pragma unroll
    for (int mt = 0; mt < 2; mt++) {
#pragma unroll
        for (int j = 0; j < 2; j++) {
            int c = (nq * 8 + j * 4 + (lane & 3)) * 2;
            float m0 = mk[c], m1 = mk[c + 1];
            float im0 = 1.f - m0, im1 = 1.f - m1;
            float bb0 = b3[c], bb1 = b3[c + 1];
#pragma unroll
            for (int rr = 0; rr < 2; rr++) {
                int r = mprow + mt * 16 + (lane >> 2) + rr * 8;
                float2* yp = (float2*)(yb + r * 68 + c);
                float2 yv = *yp;
                float d0 = acc[mt][j][rr * 2], d1 = acc[mt][j][rr * 2 + 1];
                if (SNET) {
                    float s0 = (tanhf_(d0 + bb0) + yv.x * m0) * sc[c];
                    float s1 = (tanhf_(d1 + bb1) + yv.y * m1) * sc[c + 1];
                    yv.x *= (m0 + im0 * __expf(s0));
                    yv.y *= (m1 + im1 * __expf(s1));
                    p[mt * 2 + rr] += im0 * s0 + im1 * s1;
                } else {
                    float t0 = d0 + bb0 + yv.x * m0;
                    float t1 = d1 + bb1 + yv.y * m1;
                    yv.x += im0 * t0; yv.y += im1 * t1;
                }
                *yp = yv;
            }
        }
    }
    if (SNET) {
#pragma unroll
        for (int k = 0; k < 4; k++) {
            p[k] += __shfl_xor_sync(0xffffffffu, p[k], 1);
            p[k] += __shfl_xor_sync(0xffffffffu, p[k], 2);
        }
        if ((lane & 3) == 0) {
#pragma unroll
            for (int k = 0; k < 4; k++) {
                int r = mprow + (k >> 1) * 16 + (lane >> 2) + (k & 1) * 8;
                ldp[r * 4 + nq] += p[k];
            }
        }
    }
}

// ---------------- main flow kernel ----------------
__global__ void __launch_bounds__(512, 1)
flow_kernel(const float* __restrict__ x, const float* __restrict__ masks,
            const float* __restrict__ sb1, const float* __restrict__ sb2,
            const float* __restrict__ sb3, const float* __restrict__ scale,
            const float* __restrict__ tb1, const float* __restrict__ tb2,
            const float* __restrict__ tb3,
            float* __restrict__ out, long long ld_off)
{
    extern __shared__ char smc[];
    const int tid = threadIdx.x, lane = tid & 31, w = tid >> 5;
    const int mprow = (w >> 2) * 32, nq = w & 3;
    const long long gb = (long long)blockIdx.x * 128;

    float* yb = (float*)(smc + O_Y);
    float* ldp = (float*)(smc + O_LDP);
    float* mkS = (float*)(smc + O_MASK);
    float* b1S = (float*)(smc + O_B1);
    float* b2S = (float*)(smc + O_B2);
    float* b3S = (float*)(smc + O_B3);
    float* scS = (float*)(smc + O_SC);

    {   // y init from x
        int r = tid >> 2, q = tid & 3;
#pragma unroll
        for (int j = 0; j < 4; j++)
            *(float4*)(yb + r * 68 + q * 16 + j * 4) =
                *(const float4*)(x + (gb + r) * 64 + q * 16 + j * 4);
        ldp[tid] = 0.f;
    }

    float acc[2][8][4];

#pragma unroll 1
    for (int layer = 0; layer < 8; layer++) {
        __syncthreads();
        if (tid < 64) mkS[tid] = masks[layer * 64 + tid];

#pragma unroll 1
        for (int net = 0; net < 2; net++) {
            __syncthreads();
            const float* B1p = (net ? tb1 : sb1) + layer * 256;
            const float* B2p = (net ? tb2 : sb2) + layer * 256;
            const float* B3p = (net ? tb3 : sb3) + layer * 64;
            if (tid < 256) { b1S[tid] = B1p[tid]; b2S[tid] = B2p[tid]; }
            if (tid < 64)  { b3S[tid] = B3p[tid]; if (!net) scS[tid] = scale[layer * 64 + tid]; }

            const unsigned char* Wb = g_wb + (size_t)(layer * 2 + net) * LNB;

            run_gemm<4, 8, 16384, true>(acc, Wb, smc, tid, lane, mprow, nq);
            epi_h<false>(acc, b1S, smc, lane, mprow, nq);

            run_gemm<16, 8, 16384, false>(acc, Wb + 65536, smc, tid, lane, mprow, nq);
            epi_h<true>(acc, b2S, smc, lane, mprow, nq);

            run_gemm<16, 2, 4096, false>(acc, Wb + 327680, smc, tid, lane, mprow, nq);
            if (net == 0) epi_g3<true>(acc, smc, lane, mprow, nq);
            else          epi_g3<false>(acc, smc, lane, mprow, nq);
        }
    }

    __syncthreads();
    {   // write y + logdet
        int r = tid >> 2, q = tid & 3;
#pragma unroll
        for (int j = 0; j < 4; j++)
            *(float4*)(out + (gb + r) * 64 + q * 16 + j * 4) =
                *(const float4*)(yb + r * 68 + q * 16 + j * 4);
        if (tid < 128)
            out[ld_off + gb + tid] =
                ldp[tid * 4] + ldp[tid * 4 + 1] + ldp[tid * 4 + 2] + ldp[tid * 4 + 3];
    }
}

// ---------------- launch ----------------
extern "C" void kernel_launch(void* const* d_in, const int* in_sizes, int n_in,
                              void* d_out, int out_size)
{
    const float* x     = (const float*)d_in[0];
    const float* masks = (const float*)d_in[1];
    const float* sW1   = (const float*)d_in[2];
    const float* sb1   = (const float*)d_in[3];
    const float* sW2   = (const float*)d_in[4];
    const float* sb2   = (const float*)d_in[5];
    const float* sW3   = (const float*)d_in[6];
    const float* sb3   = (const float*)d_in[7];
    const float* scale = (const float*)d_in[8];
    const float* tW1   = (const float*)d_in[9];
    const float* tb1   = (const float*)d_in[10];
    const float* tW2   = (const float*)d_in[11];
    const float* tb2   = (const float*)d_in[12];
    const float* tW3   = (const float*)d_in[13];
    const float* tb3   = (const float*)d_in[14];

    const int B = in_sizes[0] / 64;
    const long long ld_off = (long long)out_size - B;

    cudaFuncSetAttribute(flow_kernel, cudaFuncAttributeMaxDynamicSharedMemorySize,
                         SMEM_REQ);

    prep<<<768, 512>>>(sW1, sW2, sW3, tW1, tW2, tW3);
    flow_kernel<<<B / 128, 512, SMEM_REQ>>>(x, masks, sb1, sb2, sb3, scale,
                                            tb1, tb2, tb3, (float*)d_out, ld_off);
}

// round 7
// speedup vs baseline: 2.7643x; 1.4114x over previous
#include <cuda_runtime.h>
#include <cuda_bf16.h>
#include <cstdint>

typedef unsigned int u32;

// ---- SMEM layout (byte offsets) ----
#define O_H    0         // uint2 h[128][130]   (bf16 hi-pair, lo-pair), stride 130
#define O_XA   133120    // uint2 xa[128][17]   compacted active-col activations
#define O_YE   150528    // float yE[128][34]   even cols of y
#define O_YO   167936    // float yO[128][34]   odd cols
#define O_LDP  185344    // float ldp[128][4]
#define SMEM_REQ 187392

#define LN4 20480        // uint4 per (layer,net) weight block
__device__ __align__(256) uint4 g_wb[16 * LN4 + 1024];   // +16KB pad for prefetch overrun

// ---------------- helpers ----------------
__device__ __forceinline__ float tanhf_(float x) {
    float e = __expf(2.0f * x);
    return 1.0f - __fdividef(2.0f, e + 1.0f);
}
__device__ __forceinline__ uint2 splitp(float v0, float v1) {
    __nv_bfloat162 h = __floats2bfloat162_rn(v0, v1);
    float h0 = __bfloat162float(h.x), h1 = __bfloat162float(h.y);
    __nv_bfloat162 l = __floats2bfloat162_rn(v0 - h0, v1 - h1);
    uint2 r; r.x = *(u32*)&h; r.y = *(u32*)&l; return r;
}
__device__ __forceinline__ float2 unpb(u32 w) {
    __nv_bfloat162 t = *(__nv_bfloat162*)&w;
    return __bfloat1622float2(t);
}
__device__ __forceinline__ void mma16816(float* d, u32 a0, u32 a1, u32 a2, u32 a3,
                                         u32 b0, u32 b1) {
    asm volatile(
        "mma.sync.aligned.m16n8k16.row.col.f32.bf16.bf16.f32 "
        "{%0,%1,%2,%3}, {%4,%5,%6,%7}, {%8,%9}, {%0,%1,%2,%3};"
        : "+f"(d[0]), "+f"(d[1]), "+f"(d[2]), "+f"(d[3])
        : "r"(a0), "r"(a1), "r"(a2), "r"(a3), "r"(b0), "r"(b1));
}
#define BARS() asm volatile("bar.sync %0, %1;" :: "r"(strip + 1), "r"(128) : "memory")

// ---------------- prep: pack weights into streaming B-fragment layout ----------------
// Per (layer,net) block of LN4 uint4: G1 @0 (K=32 compacted, 2ks x 32nt x 32lane),
// G2 @2048 (16ks x 32nt x 32), G3 @18432 (N=32 compacted, 16ks x 4nt x 32).
// Frag uint4 = {b0hi, b1hi, b0lo, b1lo}.
__global__ void prep(const float* __restrict__ sW1, const float* __restrict__ sW2,
                     const float* __restrict__ sW3, const float* __restrict__ tW1,
                     const float* __restrict__ tW2, const float* __restrict__ tW3)
{
    int t = blockIdx.x * blockDim.x + threadIdx.x;
    if (t >= 16 * LN4) return;
    int ln = t / LN4, rem = t % LN4;
    int layer = ln >> 1, net = ln & 1;
    float w0, w1, w8, w9;
    if (rem < 2048) {                       // G1: A cols compacted to mask-active dims
        int ks = rem >> 10, nt = (rem >> 5) & 31, lane = rem & 31;
        int par = layer & 1;
        const float* wr = (net ? tW1 : sW1) + (size_t)layer * 16384
                        + (nt * 8 + (lane >> 2)) * 64 + (ks * 16 + (lane & 3) * 2) * 2 + par;
        w0 = wr[0]; w1 = wr[2]; w8 = wr[16]; w9 = wr[18];
    } else if (rem < 18432) {               // G2 dense
        int q = rem - 2048;
        int ks = q >> 10, nt = (q >> 5) & 31, lane = q & 31;
        const float* wr = (net ? tW2 : sW2) + (size_t)layer * 65536
                        + (nt * 8 + (lane >> 2)) * 256 + ks * 16 + (lane & 3) * 2;
        w0 = wr[0]; w1 = wr[1]; w8 = wr[8]; w9 = wr[9];
    } else {                                // G3: only rows for (1-m)=1 output dims
        int q = rem - 18432;
        int ks = q >> 7, nt = (q >> 5) & 3, lane = q & 31;
        int op = (layer & 1) ^ 1;
        const float* wr = (net ? tW3 : sW3) + (size_t)layer * 16384
                        + (2 * (nt * 8 + (lane >> 2)) + op) * 256 + ks * 16 + (lane & 3) * 2;
        w0 = wr[0]; w1 = wr[1]; w8 = wr[8]; w9 = wr[9];
    }
    uint2 p0 = splitp(w0, w1), p1 = splitp(w8, w9);
    g_wb[t] = make_uint4(p0.x, p1.x, p0.y, p1.y);
}

// ---------------- GEMM, 8 n-tiles/warp, B streamed from global with prefetch ----------------
template<int KS, int AST>
__device__ __forceinline__ void gemm8(float (&acc)[2][8][4],
                                      const uint4* __restrict__ Bw,
                                      const uint2* __restrict__ Arow, int lane)
{
#pragma unroll
    for (int mt = 0; mt < 2; mt++)
#pragma unroll
        for (int j = 0; j < 8; j++)
#pragma unroll
            for (int i = 0; i < 4; i++) acc[mt][j][i] = 0.f;

    uint4 bf[4];
#pragma unroll
    for (int j4 = 0; j4 < 4; j4++) bf[j4] = Bw[j4 * 32];
    const uint2* ap = Arow + (lane >> 2) * AST + (lane & 3);

#pragma unroll 1
    for (int ks = 0; ks < KS; ks++) {
        u32 Ah[2][4], Al[2][4];
#pragma unroll
        for (int mt = 0; mt < 2; mt++) {
            const uint2* p = ap + mt * (16 * AST) + ks * 8;
            uint2 t0 = p[0], t2 = p[4], t1 = p[8 * AST], t3 = p[8 * AST + 4];
            Ah[mt][0] = t0.x; Al[mt][0] = t0.y;
            Ah[mt][1] = t1.x; Al[mt][1] = t1.y;
            Ah[mt][2] = t2.x; Al[mt][2] = t2.y;
            Ah[mt][3] = t3.x; Al[mt][3] = t3.y;
        }
        const uint4* bq = Bw + ks * 1024;
#pragma unroll
        for (int j4 = 0; j4 < 4; j4++) {
            uint4 b = bf[j4]; bf[j4] = bq[(4 + j4) * 32];
#pragma unroll
            for (int mt = 0; mt < 2; mt++) {
                mma16816(acc[mt][j4], Ah[mt][0], Ah[mt][1], Ah[mt][2], Ah[mt][3], b.x, b.y);
                mma16816(acc[mt][j4], Al[mt][0], Al[mt][1], Al[mt][2], Al[mt][3], b.x, b.y);
                mma16816(acc[mt][j4], Ah[mt][0], Ah[mt][1], Ah[mt][2], Ah[mt][3], b.z, b.w);
            }
        }
#pragma unroll
        for (int j4 = 0; j4 < 4; j4++) {
            uint4 b = bf[j4]; bf[j4] = bq[1024 + j4 * 32];
#pragma unroll
            for (int mt = 0; mt < 2; mt++) {
                mma16816(acc[mt][4 + j4], Ah[mt][0], Ah[mt][1], Ah[mt][2], Ah[mt][3], b.x, b.y);
                mma16816(acc[mt][4 + j4], Al[mt][0], Al[mt][1], Al[mt][2], Al[mt][3], b.x, b.y);
                mma16816(acc[mt][4 + j4], Ah[mt][0], Ah[mt][1], Ah[mt][2], Ah[mt][3], b.z, b.w);
            }
        }
    }
}

// G3: 1 n-tile/warp (N=32 compacted), K=256
__device__ __forceinline__ void gemm1(float (&acc)[2][8][4],
                                      const uint4* __restrict__ Bw,
                                      const uint2* __restrict__ Arow, int lane)
{
#pragma unroll
    for (int mt = 0; mt < 2; mt++)
#pragma unroll
        for (int i = 0; i < 4; i++) acc[mt][0][i] = 0.f;
    uint4 bf = Bw[0];
    const uint2* ap = Arow + (lane >> 2) * 130 + (lane & 3);
#pragma unroll 1
    for (int ks = 0; ks < 16; ks++) {
        uint4 b = bf; bf = Bw[(ks + 1) * 128];
#pragma unroll
        for (int mt = 0; mt < 2; mt++) {
            const uint2* p = ap + mt * (16 * 130) + ks * 8;
            uint2 t0 = p[0], t2 = p[4], t1 = p[8 * 130], t3 = p[8 * 130 + 4];
            mma16816(acc[mt][0], t0.x, t1.x, t2.x, t3.x, b.x, b.y);
            mma16816(acc[mt][0], t0.y, t1.y, t2.y, t3.y, b.x, b.y);
            mma16816(acc[mt][0], t0.x, t1.x, t2.x, t3.x, b.z, b.w);
        }
    }
}

// epilogue for G1/G2: h = tanh(D + bias (+ h_in if RES)), split to hi/lo pairs
template<bool RES>
__device__ __forceinline__ void epi_h(float (&acc)[2][8][4],
                                      const float* __restrict__ biasg,
                                      uint2* __restrict__ hB,
                                      int lane, int mprow, int nq)
{
#pragma unroll
    for (int j = 0; j < 8; j++) {
        int c2 = nq * 32 + j * 4 + (lane & 3);
        float2 bb = *(const float2*)(biasg + 2 * c2);
#pragma unroll
        for (int mt = 0; mt < 2; mt++) {
            uint2* p = hB + (mprow + mt * 16 + (lane >> 2)) * 130 + c2;
            float u0 = acc[mt][j][0] + bb.x, u1 = acc[mt][j][1] + bb.y;
            float u2 = acc[mt][j][2] + bb.x, u3 = acc[mt][j][3] + bb.y;
            if (RES) {
                uint2 q0 = p[0], q1 = p[8 * 130];
                float2 h0 = unpb(q0.x), l0 = unpb(q0.y);
                float2 h1 = unpb(q1.x), l1 = unpb(q1.y);
                u0 += h0.x + l0.x; u1 += h0.y + l0.y;
                u2 += h1.x + l1.x; u3 += h1.y + l1.y;
            }
            p[0]       = splitp(tanhf_(u0), tanhf_(u1));
            p[8 * 130] = splitp(tanhf_(u2), tanhf_(u3));
        }
    }
}

// ---------------- main flow kernel ----------------
__global__ void __launch_bounds__(512, 1)
flow_kernel(const float* __restrict__ x,
            const float* __restrict__ sb1, const float* __restrict__ sb2,
            const float* __restrict__ sb3, const float* __restrict__ scale,
            const float* __restrict__ tb1, const float* __restrict__ tb2,
            const float* __restrict__ tb3,
            float* __restrict__ out, long long ld_off)
{
    extern __shared__ char smc[];
    uint2* hB  = (uint2*)(smc + O_H);
    uint2* xaB = (uint2*)(smc + O_XA);
    float* yE  = (float*)(smc + O_YE);
    float* yO  = (float*)(smc + O_YO);
    float* ldp = (float*)(smc + O_LDP);

    const int tid = threadIdx.x, lane = tid & 31, w = tid >> 5;
    const int strip = w >> 2, nq = w & 3, mprow = strip * 32;
    const long long gb = (long long)blockIdx.x * 128;

    {   // init: y split storage + compacted xa (layer 0 active = even cols)
        int r = tid >> 2, q = tid & 3;
        const float4* xr = (const float4*)(x + (gb + r) * 64) + q * 4;
#pragma unroll
        for (int i = 0; i < 4; i++) {
            float4 v = xr[i];
            int j = q * 8 + 2 * i;
            yE[r * 34 + j]     = v.x; yO[r * 34 + j]     = v.y;
            yE[r * 34 + j + 1] = v.z; yO[r * 34 + j + 1] = v.w;
            xaB[r * 17 + q * 4 + i] = splitp(v.x, v.z);
        }
    }
    __syncthreads();

    float ldacc[4] = {0.f, 0.f, 0.f, 0.f};
    float acc[2][8][4];
    float sreg[8];

#pragma unroll 1
    for (int layer = 0; layer < 8; layer++) {
        int op = (layer & 1) ^ 1;
#pragma unroll 1
        for (int net = 0; net < 2; net++) {
            const uint4* Wb = g_wb + (size_t)(layer * 2 + net) * LN4;
            const float* b1g = (net ? tb1 : sb1) + layer * 256;
            const float* b2g = (net ? tb2 : sb2) + layer * 256;
            const float* b3g = (net ? tb3 : sb3) + layer * 64;

            BARS();
            gemm8<2, 17>(acc, Wb + nq * 256 + lane, xaB + mprow * 17, lane);
            epi_h<false>(acc, b1g, hB, lane, mprow, nq);
            BARS();
            gemm8<16, 130>(acc, Wb + 2048 + nq * 256 + lane, hB + mprow * 130, lane);
            BARS();
            epi_h<true>(acc, b2g, hB, lane, mprow, nq);
            BARS();
            gemm1(acc, Wb + 18432 + nq * 32 + lane, hB + mprow * 130, lane);

            int a = nq * 8 + (lane & 3) * 2;
            int c0 = 2 * a + op;
            float b30 = b3g[c0], b31 = b3g[c0 + 2];
            if (net == 0) {     // s-net: xm=0 at active-out dims -> s = tanh(D+b3)*sc
                const float* scg = scale + layer * 64;
                float sc0 = scg[c0], sc1 = scg[c0 + 2];
#pragma unroll
                for (int mt = 0; mt < 2; mt++)
#pragma unroll
                    for (int rr = 0; rr < 2; rr++) {
                        float s0 = tanhf_(acc[mt][0][rr * 2]     + b30) * sc0;
                        float s1 = tanhf_(acc[mt][0][rr * 2 + 1] + b31) * sc1;
                        sreg[mt * 4 + rr * 2]     = s0;
                        sreg[mt * 4 + rr * 2 + 1] = s1;
                        ldacc[mt * 2 + rr] += s0 + s1;
                    }
            } else {            // t-net: y2 = y*exp(s) + (D+b3); write y + next layer's xa
                float* yP = op ? yO : yE;
#pragma unroll
                for (int mt = 0; mt < 2; mt++)
#pragma unroll
                    for (int rr = 0; rr < 2; rr++) {
                        int r = mprow + mt * 16 + (lane >> 2) + rr * 8;
                        float2 yv = *(float2*)(yP + r * 34 + a);
                        float y0 = yv.x * __expf(sreg[mt * 4 + rr * 2])
                                 + acc[mt][0][rr * 2] + b30;
                        float y1 = yv.y * __expf(sreg[mt * 4 + rr * 2 + 1])
                                 + acc[mt][0][rr * 2 + 1] + b31;
                        *(float2*)(yP + r * 34 + a) = make_float2(y0, y1);
                        xaB[r * 17 + nq * 4 + (lane & 3)] = splitp(y0, y1);
                    }
            }
        }
    }

    // logdet: reduce over cols (lanes sharing lane>>2), then over nq via SMEM
#pragma unroll
    for (int k = 0; k < 4; k++) {
        ldacc[k] += __shfl_xor_sync(0xffffffffu, ldacc[k], 1);
        ldacc[k] += __shfl_xor_sync(0xffffffffu, ldacc[k], 2);
    }
    if ((lane & 3) == 0) {
#pragma unroll
        for (int k = 0; k < 4; k++) {
            int r = mprow + (k >> 1) * 16 + (lane >> 2) + (k & 1) * 8;
            ldp[r * 4 + nq] = ldacc[k];
        }
    }
    __syncthreads();
    {
        int r = tid >> 2, q = tid & 3;
        float4* orow = (float4*)(out + (gb + r) * 64) + q * 4;
#pragma unroll
        for (int i = 0; i < 4; i++) {
            int j = q * 8 + 2 * i;
            orow[i] = make_float4(yE[r * 34 + j], yO[r * 34 + j],
                                  yE[r * 34 + j + 1], yO[r * 34 + j + 1]);
        }
        if (tid < 128)
            out[ld_off + gb + tid] = ldp[tid * 4] + ldp[tid * 4 + 1]
                                   + ldp[tid * 4 + 2] + ldp[tid * 4 + 3];
    }
}

// ---------------- launch ----------------
extern "C" void kernel_launch(void* const* d_in, const int* in_sizes, int n_in,
                              void* d_out, int out_size)
{
    const float* x     = (const float*)d_in[0];
    const float* sW1   = (const float*)d_in[2];
    const float* sb1   = (const float*)d_in[3];
    const float* sW2   = (const float*)d_in[4];
    const float* sb2   = (const float*)d_in[5];
    const float* sW3   = (const float*)d_in[6];
    const float* sb3   = (const float*)d_in[7];
    const float* scale = (const float*)d_in[8];
    const float* tW1   = (const float*)d_in[9];
    const float* tb1   = (const float*)d_in[10];
    const float* tW2   = (const float*)d_in[11];
    const float* tb2   = (const float*)d_in[12];
    const float* tW3   = (const float*)d_in[13];
    const float* tb3   = (const float*)d_in[14];

    const int B = in_sizes[0] / 64;
    const long long ld_off = (long long)out_size - B;

    cudaFuncSetAttribute(flow_kernel, cudaFuncAttributeMaxDynamicSharedMemorySize,
                         SMEM_REQ);

    prep<<<1280, 256>>>(sW1, sW2, sW3, tW1, tW2, tW3);
    flow_kernel<<<B / 128, 512, SMEM_REQ>>>(x, sb1, sb2, sb3, scale,
                                            tb1, tb2, tb3, (float*)d_out, ld_off);
}